// round 17
// baseline (speedup 1.0000x reference)
#include <cuda_runtime.h>
#include <cuda_fp16.h>
#include <cstdint>
#include <math.h>

typedef unsigned int u32;

#define DM   1024
#define G4   4096
#define NB   128
#define NS   1024
#define NC   512
#define NCTA 128
#define PH_STEP 65536

// ---------------- device scratch (static, no allocation) ----------------
__device__ float g_G[NC * G4];              // 8 MB
__device__ u32   g_PH[NS * PH_STEP];        // 256 MB fp16 h history, fragment-packed
__device__ uint4 g_WpPack[8 * 64 * 4 * 32]; // 1 MB W_pred fp16 B-fragment order
__device__ int   g_bar[NS * 256];           // 8 spread counters/step (stride 32)

// ============ fp32 NT GEMM for G (known-good) ============
__global__ void gemm_nt_kernel(const float* __restrict__ A, const float* __restrict__ Bm,
                               const float* __restrict__ bias0, const float* __restrict__ bias1,
                               float* __restrict__ Cout, int M, int N, int K)
{
    __shared__ float As[16][64];
    __shared__ float Bs[16][64];
    const int tid = threadIdx.x;
    const int tx = tid & 15, ty = tid >> 4;
    const int mBase = blockIdx.x * 64, nBase = blockIdx.y * 64;
    const int la = tid >> 2, lk = (tid & 3) * 4;

    float acc[4][4];
#pragma unroll
    for (int i = 0; i < 4; i++)
#pragma unroll
        for (int j = 0; j < 4; j++) acc[i][j] = 0.f;

    for (int kc = 0; kc < K; kc += 16) {
        {
            float4 v = *reinterpret_cast<const float4*>(&A[(size_t)(mBase + la) * K + kc + lk]);
            As[lk + 0][la] = v.x; As[lk + 1][la] = v.y; As[lk + 2][la] = v.z; As[lk + 3][la] = v.w;
        }
        {
            float4 v = *reinterpret_cast<const float4*>(&Bm[(size_t)(nBase + la) * K + kc + lk]);
            Bs[lk + 0][la] = v.x; Bs[lk + 1][la] = v.y; Bs[lk + 2][la] = v.z; Bs[lk + 3][la] = v.w;
        }
        __syncthreads();
#pragma unroll
        for (int k = 0; k < 16; k++) {
            float4 a4 = *reinterpret_cast<const float4*>(&As[k][tx * 4]);
            float4 b4 = *reinterpret_cast<const float4*>(&Bs[k][ty * 4]);
            float a[4] = {a4.x, a4.y, a4.z, a4.w};
            float b[4] = {b4.x, b4.y, b4.z, b4.w};
#pragma unroll
            for (int i = 0; i < 4; i++)
#pragma unroll
                for (int j = 0; j < 4; j++)
                    acc[i][j] = fmaf(a[i], b[j], acc[i][j]);
        }
        __syncthreads();
    }
#pragma unroll
    for (int i = 0; i < 4; i++) {
        int row = mBase + tx * 4 + i;
#pragma unroll
        for (int j = 0; j < 4; j++) {
            int col = nBase + ty * 4 + j;
            Cout[(size_t)row * N + col] = acc[i][j] + bias0[col] + bias1[col];
        }
    }
}

// ---- fast, saturating-safe activations ----
__device__ __forceinline__ float fast_sigmoid(float x) { return 1.f / (1.f + __expf(-x)); }
__device__ __forceinline__ float fast_tanh(float x)    { return 1.f - 2.f / (1.f + __expf(2.f * x)); }

#define MMA16816(C, A0, A1, A2, A3, B0, B1)                                   \
    asm volatile(                                                             \
        "mma.sync.aligned.m16n8k16.row.col.f32.f16.f16.f32 "                  \
        "{%0,%1,%2,%3}, {%4,%5,%6,%7}, {%8,%9}, {%0,%1,%2,%3};"               \
        : "+f"(C[0]), "+f"(C[1]), "+f"(C[2]), "+f"(C[3])                      \
        : "r"(A0), "r"(A1), "r"(A2), "r"(A3), "r"(B0), "r"(B1))

// ============ pack W_pred -> fp16 B-fragment order (known-good) ============
__global__ void pack_wpred_kernel(const float* __restrict__ Wp)
{
    int idx = blockIdx.x * 256 + threadIdx.x;
    int lane = idx & 31, q = (idx >> 5) & 3, it = (idx >> 7) & 63, nb = idx >> 13;
    u32 v[4];
#pragma unroll
    for (int h = 0; h < 2; h++) {
        int t = 2 * q + h;
        int n = nb * 64 + t * 8 + (lane >> 2);
        const float* row = Wp + (size_t)n * DM;
        int j0 = it * 8 + (lane & 3), j1 = j0 + 4;
        __half2 p0 = __floats2half2_rn(row[2 * j0], row[2 * j0 + 1]);
        __half2 p1 = __floats2half2_rn(row[2 * j1], row[2 * j1 + 1]);
        v[2 * h + 0] = *reinterpret_cast<u32*>(&p0);
        v[2 * h + 1] = *reinterpret_cast<u32*>(&p1);
    }
    g_WpPack[idx] = make_uint4(v[0], v[1], v[2], v[3]);
}

// =========================================================================
// Persistent LSTM, L2-halving tiling:
//   CTA = (bi = cta&1 batch half [64bi,64bi+64), dj = cta>>1 d-block of 16).
//   Warp w = (kh = w>>2 K-half, g = w&3 gate): M=64 (4 mtiles), N=16 (2 nt),
//   K=512 (32 iters). W fragments in regs (128 u32). Unique h read per CTA =
//   128 KB/step (vs 256 KB) -> chip 16 MB/step. Split-K=2 smem reduce.
//   Cell: thread owns (1 batch, 4 d), c in 4 regs. R10 barrier. PH unchanged.
// =========================================================================
#define RSTRIDE 68
#define RED_FLOATS (2 * 64 * RSTRIDE)   // 8704 floats = 34816 B

__global__ void __launch_bounds__(256, 1)
lstm_mma_kernel(const int* __restrict__ x, const float* __restrict__ Whh)
{
    extern __shared__ float red[];

    const int tid  = threadIdx.x;
    const int lane = tid & 31;
    const int w    = tid >> 5;          // 0..7
    const int kh   = w >> 2;            // K half
    const int g    = w & 3;             // gate
    const int cta  = blockIdx.x;
    const int bi   = cta & 1;           // batch half
    const int dj   = cta >> 1;          // d block (16 d)
    const int tig  = lane & 3;
    const int grp  = lane >> 2;

    // ---- one-time: W_hh fragments -> registers ----
    // warp (kh, g): rows = gate g, d in [16dj, 16dj+16) (2 ntiles), K half kh.
    u32 wreg[128];
    {
        const int kbase = kh * 512 + 2 * tig;
#pragma unroll
        for (int it = 0; it < 32; it++) {
#pragma unroll
            for (int nt = 0; nt < 2; nt++) {
                const float* Wr = Whh
                    + (size_t)(g * DM + 16 * dj + nt * 8 + grp) * DM + kbase + it * 16;
                __half2 p0 = __floats2half2_rn(Wr[0], Wr[1]);
                __half2 p1 = __floats2half2_rn(Wr[8], Wr[9]);
                wreg[it * 4 + nt * 2 + 0] = *reinterpret_cast<u32*>(&p0);
                wreg[it * 4 + nt * 2 + 1] = *reinterpret_cast<u32*>(&p1);
            }
        }
    }

    // ---- A-fragment bases: mtile m covers batches 64bi+16m+... ----
    int aBase[4];
#pragma unroll
    for (int m = 0; m < 4; m++)
        aBase[m] = ((4 * bi + m) * 8 + grp) * 1024 + 4 * tig + kh * 512;

    // ---- cell-update ownership: thread -> (batch lb, 4 d at ld0) ----
    const int lb  = tid & 63;
    const int ld0 = (tid >> 6) * 4;
    const int bglob = 64 * bi + lb;
    const int pair  = (bglob >> 4) * 8 + (lb & 7);
    const int hi    = (lb >> 3) & 1;
    // PH u32 indices for the two h2 outputs (k2 = 8*dj + ld0/2 + j)
    int phIdx[2];
#pragma unroll
    for (int j = 0; j < 2; j++) {
        int k2 = 8 * dj + (ld0 >> 1) + j;
        int p8 = k2 & 7;
        int slot = (p8 < 4) ? (2 * p8) : (2 * (p8 - 4) + 1);
        phIdx[j] = pair * 1024 + ((k2 >> 3) * 8 + slot) * 2 + hi;
    }

    float cr[4] = {0.f, 0.f, 0.f, 0.f};

    for (int s = 0; s < NS; s++) {
        float acc[4][2][4];             // [mtile][ntile][c]
#pragma unroll
        for (int m = 0; m < 4; m++)
#pragma unroll
            for (int nt = 0; nt < 2; nt++)
#pragma unroll
                for (int c = 0; c < 4; c++) acc[m][nt][c] = 0.f;

        if (s > 0) {
            const u32* ph = g_PH + (size_t)(s - 1) * PH_STEP;
#pragma unroll 4
            for (int it = 0; it < 32; it++) {
                uint4 a0 = *reinterpret_cast<const uint4*>(ph + aBase[0] + it * 16);
                uint4 a1 = *reinterpret_cast<const uint4*>(ph + aBase[1] + it * 16);
                uint4 a2 = *reinterpret_cast<const uint4*>(ph + aBase[2] + it * 16);
                uint4 a3 = *reinterpret_cast<const uint4*>(ph + aBase[3] + it * 16);
#pragma unroll
                for (int nt = 0; nt < 2; nt++) {
                    u32 w0 = wreg[it * 4 + nt * 2], w1 = wreg[it * 4 + nt * 2 + 1];
                    MMA16816(acc[0][nt], a0.x, a0.y, a0.z, a0.w, w0, w1);
                    MMA16816(acc[1][nt], a1.x, a1.y, a1.z, a1.w, w0, w1);
                    MMA16816(acc[2][nt], a2.x, a2.y, a2.z, a2.w, w0, w1);
                    MMA16816(acc[3][nt], a3.x, a3.y, a3.z, a3.w, w0, w1);
                }
            }
        }

        // ---- publish split-K partials: red[kh][row 0..63][col 0..63] ----
        {
            float* rq = red + kh * (64 * RSTRIDE);
#pragma unroll
            for (int m = 0; m < 4; m++) {
                int r0 = 16 * m + grp;
#pragma unroll
                for (int nt = 0; nt < 2; nt++) {
                    int col = g * 16 + nt * 8 + 2 * tig;
                    *reinterpret_cast<float2*>(rq + r0 * RSTRIDE + col) =
                        make_float2(acc[m][nt][0], acc[m][nt][1]);
                    *reinterpret_cast<float2*>(rq + (r0 + 8) * RSTRIDE + col) =
                        make_float2(acc[m][nt][2], acc[m][nt][3]);
                }
            }
        }
        __syncthreads();

        // ---- reduce 2 halves + thread-local LSTM cell update ----
        {
            const int xv = __ldg(&x[s * NB + bglob]);
            const float* Gr = g_G + (size_t)xv * G4 + 16 * dj + ld0;

            float av[4][4];             // [gate][e]
#pragma unroll
            for (int gg = 0; gg < 4; gg++) {
                float4 s0 = *reinterpret_cast<const float4*>(
                    red + 0 * (64 * RSTRIDE) + lb * RSTRIDE + gg * 16 + ld0);
                float4 s1 = *reinterpret_cast<const float4*>(
                    red + 1 * (64 * RSTRIDE) + lb * RSTRIDE + gg * 16 + ld0);
                float4 gv = *reinterpret_cast<const float4*>(Gr + gg * DM);
                av[gg][0] = s0.x + s1.x + gv.x;
                av[gg][1] = s0.y + s1.y + gv.y;
                av[gg][2] = s0.z + s1.z + gv.z;
                av[gg][3] = s0.w + s1.w + gv.w;
            }

            float hv[4];
#pragma unroll
            for (int e = 0; e < 4; e++) {
                float iv = fast_sigmoid(av[0][e]);
                float fv = fast_sigmoid(av[1][e]);
                float gv = fast_tanh(av[2][e]);
                float ov = fast_sigmoid(av[3][e]);
                float cnew = fmaf(fv, cr[e], iv * gv);
                cr[e] = cnew;
                hv[e] = ov * fast_tanh(cnew);
            }
            __half2 h0 = __floats2half2_rn(hv[0], hv[1]);
            __half2 h1 = __floats2half2_rn(hv[2], hv[3]);
            u32* phw = g_PH + (size_t)s * PH_STEP;
            phw[phIdx[0]] = *reinterpret_cast<u32*>(&h0);
            phw[phIdx[1]] = *reinterpret_cast<u32*>(&h1);
        }

        // ---- grid barrier: 8 spread counters, lane-parallel poll (proven R10) ----
        __syncthreads();
        __threadfence();
        if (w == 0) {
            if (lane == 0)
                atomicAdd(&g_bar[s * 256 + (cta & 7) * 32], 1);
            int done;
            do {
                int v = (lane < 8)
                      ? *((volatile int*)&g_bar[s * 256 + lane * 32]) : 16;
                done = __all_sync(0xffffffffu, v >= 16);
            } while (!done);
        }
        __syncthreads();
        __threadfence();
    }
}

// Reset barrier counters for deterministic graph replay.
__global__ void reset_bar_kernel()
{
    g_bar[blockIdx.x * 256 + threadIdx.x] = 0;
}

// ============ logits: PH(fp16) @ W_pred^T + bias via warp mma (known-good) ============
__global__ void __launch_bounds__(256, 1)
logits_mma_kernel(const float* __restrict__ bias, float* __restrict__ out)
{
    extern __shared__ uint4 wb[];        // 8192 uint4 = 128 KB
    const int tid = threadIdx.x;
    const int lane = tid & 31, w = tid >> 5;
    const int nb = blockIdx.x, s = blockIdx.y;
    const int grp = lane >> 2, tig = lane & 3;

    for (int i = tid; i < 8192; i += 256) wb[i] = g_WpPack[nb * 8192 + i];
    __syncthreads();

    const u32* ph   = g_PH + (size_t)s * PH_STEP;
    const int aBase = (w * 8 + grp) * 1024 + 4 * tig;

    float acc[8][4];
#pragma unroll
    for (int t = 0; t < 8; t++)
#pragma unroll
        for (int j = 0; j < 4; j++) acc[t][j] = 0.f;

#pragma unroll 2
    for (int it = 0; it < 64; it++) {
        uint4 a = *reinterpret_cast<const uint4*>(ph + aBase + it * 16);
#pragma unroll
        for (int qq = 0; qq < 4; qq++) {
            uint4 wq = wb[it * 128 + qq * 32 + lane];
            MMA16816(acc[2 * qq],     a.x, a.y, a.z, a.w, wq.x, wq.y);
            MMA16816(acc[2 * qq + 1], a.x, a.y, a.z, a.w, wq.z, wq.w);
        }
    }

    const int bL = w * 16 + grp, bH = bL + 8;
#pragma unroll
    for (int t = 0; t < 8; t++) {
        int col = nb * 64 + t * 8 + 2 * tig;
        float2 bz = *reinterpret_cast<const float2*>(bias + col);
        *reinterpret_cast<float2*>(out + (size_t)bL * NS * NC + (size_t)s * NC + col) =
            make_float2(acc[t][0] + bz.x, acc[t][1] + bz.y);
        *reinterpret_cast<float2*>(out + (size_t)bH * NS * NC + (size_t)s * NC + col) =
            make_float2(acc[t][2] + bz.x, acc[t][3] + bz.y);
    }
}

// =========================================================================
extern "C" void kernel_launch(void* const* d_in, const int* in_sizes, int n_in,
                              void* d_out, int out_size)
{
    const int*   x      = (const int*)  d_in[0];
    const float* emb    = (const float*)d_in[1];
    const float* W_ih   = (const float*)d_in[2];
    const float* W_hh   = (const float*)d_in[3];
    const float* b_ih   = (const float*)d_in[4];
    const float* b_hh   = (const float*)d_in[5];
    const float* W_pred = (const float*)d_in[6];
    const float* b_pred = (const float*)d_in[7];
    float* out = (float*)d_out;

    float* Gp; cudaGetSymbolAddress((void**)&Gp, g_G);

    // 1) G = emb @ W_ih^T + b_ih + b_hh
    {
        dim3 grid(NC / 64, G4 / 64);
        gemm_nt_kernel<<<grid, 256>>>(emb, W_ih, b_ih, b_hh, Gp, NC, G4, DM);
    }
    // 2) pack W_pred
    pack_wpred_kernel<<<256, 256>>>(W_pred);
    // 3) persistent LSTM (L2-halving tiling)
    {
        const int smem_bytes = RED_FLOATS * (int)sizeof(float);   // 34816
        cudaFuncSetAttribute(lstm_mma_kernel,
                             cudaFuncAttributeMaxDynamicSharedMemorySize, smem_bytes);
        lstm_mma_kernel<<<NCTA, 256, smem_bytes>>>(x, W_hh);
    }
    // 4) reset barrier counters
    reset_bar_kernel<<<NS, 256>>>();
    // 5) logits
    {
        const int smem_bytes = 8192 * (int)sizeof(uint4);
        cudaFuncSetAttribute(logits_mma_kernel,
                             cudaFuncAttributeMaxDynamicSharedMemorySize, smem_bytes);
        dim3 grid(8, NS);
        logits_mma_kernel<<<grid, 256, smem_bytes>>>(b_pred, out);
    }
}